// round 2
// baseline (speedup 1.0000x reference)
#include <cuda_runtime.h>
#include <cuda_bf16.h>
#include <cstdint>

#define Bn 128
#define Tn 256
#define NHID 1024
#define NIN 128
#define NOUT 64
#define KTOT 1152
#define NCTA 128
#define THREADS 128

// output layout: hidden_list [128][256][1024] ++ output_list [128][256][64] ++ h_final [128][1024]
#define OUT_HID 0
#define OUT_OUT 33554432
#define OUT_HF  35651584

// -------- device scratch (no allocations allowed) --------
__device__ float g_act[2][NHID * Bn];            // tanh(h), [k][b], double buffered
__device__ float g_xT[Tn * NIN * Bn];            // x transposed per t: [t][i][b]
__device__ float g_outpart[2][32 * Bn * NOUT];   // out partials [jg][b][o]
__device__ unsigned g_arrive;
__device__ unsigned g_release;

// -------- helpers --------
typedef unsigned long long ull;

__device__ __forceinline__ ull pack2(float x) {
    ull r; asm("mov.b64 %0, {%1, %1};" : "=l"(r) : "f"(x)); return r;
}
__device__ __forceinline__ void fma2(ull& c, ull a, ull b) {
    asm("fma.rn.f32x2 %0, %1, %2, %0;" : "+l"(c) : "l"(a), "l"(b));
}
__device__ __forceinline__ float2 unpack2(ull v) {
    float2 f; asm("mov.b64 {%0, %1}, %2;" : "=f"(f.x), "=f"(f.y) : "l"(v)); return f;
}
__device__ __forceinline__ void cpasync16(uint32_t dst, const float* src) {
    asm volatile("cp.async.cg.shared.global [%0], [%1], 16;" :: "r"(dst), "l"(src));
}
__device__ __forceinline__ void cpcommit() { asm volatile("cp.async.commit_group;"); }
template<int N> __device__ __forceinline__ void cpwait() {
    asm volatile("cp.async.wait_group %0;" :: "n"(N));
}

// -------- x transpose: g_xT[t][i][b] = input_signal[b][t][i] --------
__global__ void xT_kernel(const float* __restrict__ in) {
    __shared__ float s[128][33];
    int t = blockIdx.x >> 2, ig = blockIdx.x & 3;
    for (int idx = threadIdx.x; idx < 128 * 32; idx += 256) {
        int b = idx >> 5, ii = idx & 31;
        s[b][ii] = in[b * (Tn * NIN) + t * NIN + ig * 32 + ii];
    }
    __syncthreads();
    for (int idx = threadIdx.x; idx < 4096; idx += 256) {
        int ii = idx >> 7, b = idx & 127;
        g_xT[t * (NIN * Bn) + (ig * 32 + ii) * Bn + b] = s[b][ii];
    }
}

// -------- persistent RNN kernel --------
// grid = 128 CTAs = 4 b-groups x 32 j-groups; 128 threads.
// smem: w_s [1152][32], act_s [2][128][32], wo_s [32][64], hj [32][36]
#define SM_W   0
#define SM_ACT (1152 * 32)
#define SM_WO  (SM_ACT + 2 * 128 * 32)
#define SM_HJ  (SM_WO + 32 * 64)
#define SM_FLOATS (SM_HJ + 32 * 36)
#define SMEM_BYTES (SM_FLOATS * 4)

__global__ void __launch_bounds__(THREADS, 1)
rnn_main(const float* __restrict__ hidden,
         const float* __restrict__ w_in,
         const float* __restrict__ w_hh,
         const float* __restrict__ w_b,
         const float* __restrict__ w_out,
         const float* __restrict__ alpha,
         const float* __restrict__ noise,
         const int* __restrict__ ptp,
         float* __restrict__ out)
{
    extern __shared__ float sm[];
    float* w_s   = sm + SM_W;
    float* act_s = sm + SM_ACT;
    float* wo_s  = sm + SM_WO;
    float* hj    = sm + SM_HJ;

    const int tid = threadIdx.x;
    const int cta = blockIdx.x;
    const int jg = cta & 31, bg = cta >> 5;
    const int jbase = jg * 32, bbase = bg * 32;

    // ---- load weight slices into smem (once) ----
    {
        int jj = tid & 31;
        int kq = tid >> 5; // 0..3
        for (int k = kq * 256; k < kq * 256 + 256; k++)
            w_s[k * 32 + jj] = w_hh[(jbase + jj) * NHID + k];
        for (int i = kq * 32; i < kq * 32 + 32; i++)
            w_s[(1024 + i) * 32 + jj] = w_in[(jbase + jj) * NIN + i];
    }
    for (int idx = tid; idx < 32 * 64; idx += THREADS) {
        int jj = idx >> 6, o = idx & 63;
        wo_s[jj * 64 + o] = w_out[o * NHID + jbase + jj];
    }

    // ---- per-thread tile: 4 b x 2 j ----
    const int bq = tid & 7, jq = tid >> 3;
    const int b0 = bq * 4, j0 = jq * 2;

    const float al0 = alpha[jbase + j0], al1 = alpha[jbase + j0 + 1];
    const float bi0 = w_b[jbase + j0],   bi1 = w_b[jbase + j0 + 1];
    const float ns0 = 0.05f * sqrtf(al0), ns1 = 0.05f * sqrtf(al1);
    const int pt = *ptp;

    // persistent h registers
    float h[4][2];
    #pragma unroll
    for (int b = 0; b < 4; b++) {
        #pragma unroll
        for (int j = 0; j < 2; j++)
            h[b][j] = hidden[(bbase + b0 + b) * NHID + jbase + j0 + j];
    }
    // initial act buffer 0 = tanh(hidden), layout [k][b]
    #pragma unroll
    for (int j = 0; j < 2; j++) {
        float4 v = make_float4(tanhf(h[0][j]), tanhf(h[1][j]), tanhf(h[2][j]), tanhf(h[3][j]));
        *(float4*)&g_act[0][(jbase + j0 + j) * Bn + bbase + b0] = v;
    }

    // grid barrier bookkeeping (monotonic, replay-safe)
    unsigned bar_t = 0;
    if (tid == 0) bar_t = *((volatile unsigned*)&g_release);

#define GRIDBAR() do {                                                        \
        __syncthreads();                                                      \
        if (tid == 0) {                                                       \
            __threadfence();                                                  \
            bar_t += (unsigned)NCTA;                                          \
            unsigned a_ = atomicAdd(&g_arrive, 1u) + 1u;                      \
            if (a_ == bar_t) { atomicExch(&g_release, bar_t); }               \
            else { while ((int)(*((volatile unsigned*)&g_release) - bar_t) < 0) {} } \
            __threadfence();                                                  \
        }                                                                     \
        __syncthreads();                                                      \
    } while (0)

    GRIDBAR();  // g_act[0] visible everywhere

    const uint32_t act_u = (uint32_t)__cvta_generic_to_shared(act_s);
    const int r0 = tid >> 3, cg = tid & 7;

    for (int t = 0; t < Tn; t++) {
        // ---- deterministic reduce of previous step's out partials ----
        if (t > 0 && tid < 64) {
            int e = cta * 64 + tid;
            const float* src = g_outpart[(t - 1) & 1];
            float s = 0.f;
            #pragma unroll
            for (int r = 0; r < 32; r++) s += src[r * 8192 + e];
            int b = e >> 6, o = e & 63;
            out[OUT_OUT + b * (Tn * NOUT) + (t - 1) * NOUT + o] = s;
        }

        const float* asrc = g_act[t & 1];
        const float* xsrc = g_xT + t * (NIN * Bn);

        ull acc00 = 0, acc01 = 0, acc10 = 0, acc11 = 0;

        // prologue: stage chunk 0
        {
            const float* src = asrc;  // chunk 0 rows 0..127
            uint32_t dst = act_u;
            #pragma unroll
            for (int s = 0; s < 8; s++) {
                int r = r0 + s * 16;
                cpasync16(dst + (uint32_t)((r * 32 + cg * 4) * 4), src + r * Bn + bbase + cg * 4);
            }
            cpcommit();
        }

        #pragma unroll 1
        for (int c = 0; c < 9; c++) {
            if (c < 8) {
                const float* src = (c + 1 < 8) ? (asrc + (c + 1) * 128 * Bn) : xsrc;
                uint32_t dst = act_u + (uint32_t)(((c + 1) & 1) * 4096 * 4);
                #pragma unroll
                for (int s = 0; s < 8; s++) {
                    int r = r0 + s * 16;
                    cpasync16(dst + (uint32_t)((r * 32 + cg * 4) * 4), src + r * Bn + bbase + cg * 4);
                }
                cpcommit();
                cpwait<1>();
            } else {
                cpwait<0>();
            }
            __syncthreads();

            const float* ab = act_s + (c & 1) * 4096 + b0;
            const float* wb = w_s + c * 128 * 32 + j0;
            #pragma unroll 8
            for (int kk = 0; kk < 128; kk++) {
                ulonglong2 aa = *(const ulonglong2*)(ab + kk * 32);
                float2 wv = *(const float2*)(wb + kk * 32);
                ull w0 = pack2(wv.x), w1 = pack2(wv.y);
                fma2(acc00, aa.x, w0); fma2(acc01, aa.x, w1);
                fma2(acc10, aa.y, w0); fma2(acc11, aa.y, w1);
            }
            __syncthreads();
        }

        // ---- h update ----
        float2 p00 = unpack2(acc00), p01 = unpack2(acc01);
        float2 p10 = unpack2(acc10), p11 = unpack2(acc11);
        float tmpv[4][2] = {{p00.x, p01.x}, {p00.y, p01.y}, {p10.x, p11.x}, {p10.y, p11.y}};

        #pragma unroll
        for (int b = 0; b < 4; b++) {
            float t0 = tmpv[b][0] + bi0;
            float t1 = tmpv[b][1] + bi1;
            h[b][0] = (1.f - al0) * h[b][0] + al0 * t0;
            h[b][1] = (1.f - al1) * h[b][1] + al1 * t1;
        }
        if (t == pt) {
            #pragma unroll
            for (int b = 0; b < 4; b++) {
                const float* np = noise + (bbase + b0 + b) * NHID + jbase + j0;
                h[b][0] += np[0] * ns0;
                h[b][1] += np[1] * ns1;
            }
        }

        // hidden_list write
        #pragma unroll
        for (int b = 0; b < 4; b++) {
            float2 v = make_float2(h[b][0], h[b][1]);
            *(float2*)&out[OUT_HID + (size_t)(bbase + b0 + b) * (Tn * NHID) + t * NHID + jbase + j0] = v;
        }
        if (t == Tn - 1) {
            #pragma unroll
            for (int b = 0; b < 4; b++) {
                float2 v = make_float2(h[b][0], h[b][1]);
                *(float2*)&out[OUT_HF + (bbase + b0 + b) * NHID + jbase + j0] = v;
            }
        }
        // next act buffer (tanh), [k][b]
        #pragma unroll
        for (int j = 0; j < 2; j++) {
            float4 v = make_float4(tanhf(h[0][j]), tanhf(h[1][j]), tanhf(h[2][j]), tanhf(h[3][j]));
            *(float4*)&g_act[(t + 1) & 1][(jbase + j0 + j) * Bn + bbase + b0] = v;
        }
        // stage h tile transposed for out-GEMM
        #pragma unroll
        for (int j = 0; j < 2; j++) {
            float4 v = make_float4(h[0][j], h[1][j], h[2][j], h[3][j]);
            *(float4*)&hj[(j0 + j) * 36 + b0] = v;
        }
        __syncthreads();

        // ---- out partial GEMM: [32b x 64o], K = 32 (this CTA's j slice) ----
        {
            const int o0 = (tid & 15) * 4, br = (tid >> 4) * 4;
            float oa[4][4] = {};
            #pragma unroll
            for (int j = 0; j < 32; j++) {
                float4 a4 = *(const float4*)&hj[j * 36 + br];
                float4 w4 = *(const float4*)&wo_s[j * 64 + o0];
                oa[0][0] += a4.x * w4.x; oa[0][1] += a4.x * w4.y; oa[0][2] += a4.x * w4.z; oa[0][3] += a4.x * w4.w;
                oa[1][0] += a4.y * w4.x; oa[1][1] += a4.y * w4.y; oa[1][2] += a4.y * w4.z; oa[1][3] += a4.y * w4.w;
                oa[2][0] += a4.z * w4.x; oa[2][1] += a4.z * w4.y; oa[2][2] += a4.z * w4.z; oa[2][3] += a4.z * w4.w;
                oa[3][0] += a4.w * w4.x; oa[3][1] += a4.w * w4.y; oa[3][2] += a4.w * w4.z; oa[3][3] += a4.w * w4.w;
            }
            float* op = g_outpart[t & 1] + jg * 8192;
            #pragma unroll
            for (int b = 0; b < 4; b++) {
                float4 v = make_float4(oa[b][0], oa[b][1], oa[b][2], oa[b][3]);
                *(float4*)&op[(bbase + br + b) * 64 + o0] = v;
            }
        }

        GRIDBAR();
    }

    // final out reduce for t = 255
    if (tid < 64) {
        int e = cta * 64 + tid;
        const float* src = g_outpart[(Tn - 1) & 1];
        float s = 0.f;
        #pragma unroll
        for (int r = 0; r < 32; r++) s += src[r * 8192 + e];
        int b = e >> 6, o = e & 63;
        out[OUT_OUT + b * (Tn * NOUT) + (Tn - 1) * NOUT + o] = s;
    }
#undef GRIDBAR
}

// -------- launcher --------
extern "C" void kernel_launch(void* const* d_in, const int* in_sizes, int n_in,
                              void* d_out, int out_size)
{
    const float* input_signal = (const float*)d_in[0];
    const float* hidden       = (const float*)d_in[1];
    const float* w_in_w       = (const float*)d_in[2];
    const float* w_hh_w       = (const float*)d_in[3];
    const float* w_hh_b       = (const float*)d_in[4];
    const float* w_out_w      = (const float*)d_in[5];
    const float* alpha        = (const float*)d_in[6];
    const float* noise_raw    = (const float*)d_in[7];
    const int*   pt           = (const int*)d_in[8];
    float* out = (float*)d_out;

    cudaFuncSetAttribute(rnn_main, cudaFuncAttributeMaxDynamicSharedMemorySize, SMEM_BYTES);

    xT_kernel<<<1024, 256>>>(input_signal);
    rnn_main<<<NCTA, THREADS, SMEM_BYTES>>>(hidden, w_in_w, w_hh_w, w_hh_b,
                                            w_out_w, alpha, noise_raw, pt, out);
}